// round 14
// baseline (speedup 1.0000x reference)
#include <cuda_runtime.h>

// RWKV v4 single-token forward, persistent kernel, round 14.
// Base = R5/R13 (best, 620us). ONE new mechanism: L2 PRIMING. Warps that are
// idle in a GEMV stage (A: 1792, B: 2816, D: 768 of 4864) issue real LDG.32
// sector reads (one 32B sector per lane, 4 instr per 4KB row) over the NEXT
// stage's weight rows, accumulated into a never-taken sink. Lines land in L2
// with normal priority; the next stage's __ldcs dots hit L2 (~250cyc) instead
// of DRAM (~600cyc) -> same in-flight, ~2x stream rate. Schedule: A primes
// B+C, B primes D, D primes next layer's A (head rows on the last layer).

#define E    1024
#define HH   4096
#define NL   24
#define NV   50277
#define T    1024
#define WPB  32
#define NPAR 16

// ---- persistent device scratch ----
__device__ float g_kvr[3 * E];
__device__ float g_op[2][E];
__device__ float g_fk[HH];
__device__ float g_frp[2][E];
__device__ float g_fvp[4][E];
__device__ float g_sink;
__device__ unsigned int g_bar[2];  // memset per launch

struct P {
    const float *ctx, *state, *ln0w, *ln0b, *ln1w, *ln1b, *ln2w, *ln2b;
    const float *td, *tf, *tmk, *tmv, *tmr, *kw, *vw, *rw, *ow;
    const float *ftmk, *ftmr, *fkw, *frw, *fvw, *lnoutw, *lnoutb, *head;
    float* out;
    int nb;
    int ws;
};

__device__ __forceinline__ void grid_sync(int nb) {
    __syncthreads();
    if (threadIdx.x == 0) {
        unsigned int gen = ((volatile unsigned int*)g_bar)[1];
        __threadfence();
        if (atomicAdd(&g_bar[0], 1u) == (unsigned int)(nb - 1)) {
            atomicExch(&g_bar[0], 0u);
            __threadfence();
            atomicAdd(&g_bar[1], 1u);
        } else {
            while (((volatile unsigned int*)g_bar)[1] == gen) { __nanosleep(64); }
        }
        __threadfence();
    }
    __syncthreads();
}

__device__ __forceinline__ void block_reduce2(float& a, float& b, float* sr) {
    #pragma unroll
    for (int o = 16; o; o >>= 1) {
        a += __shfl_down_sync(0xFFFFFFFFu, a, o);
        b += __shfl_down_sync(0xFFFFFFFFu, b, o);
    }
    int w = threadIdx.x >> 5, l = threadIdx.x & 31;
    __syncthreads();
    if (l == 0) { sr[w] = a; sr[w + WPB] = b; }
    __syncthreads();
    if (threadIdx.x == 0) {
        float sa = 0.f, sb2 = 0.f;
        #pragma unroll
        for (int i = 0; i < WPB; i++) { sa += sr[i]; sb2 += sr[i + WPB]; }
        sr[2 * WPB] = sa; sr[2 * WPB + 1] = sb2;
    }
    __syncthreads();
    a = sr[2 * WPB];
    b = sr[2 * WPB + 1];
}

// warp dot over 128*N4 floats; weights streamed with .cs (read-once)
template <int N4>
__device__ __forceinline__ float warp_dot(const float* __restrict__ w,
                                          const float* x, int lane) {
    const float4* __restrict__ w4 = (const float4*)w;
    const float4* x4 = (const float4*)x;
    float a0 = 0.f, a1 = 0.f, a2 = 0.f, a3 = 0.f;
    #pragma unroll
    for (int u = 0; u < N4; u += 4) {
        float4 wa = __ldcs(&w4[lane + 32 * u]);
        float4 xa = x4[lane + 32 * u];
        a0 += wa.x * xa.x + wa.y * xa.y + wa.z * xa.z + wa.w * xa.w;
        if (u + 1 < N4) {
            float4 wb = __ldcs(&w4[lane + 32 * (u + 1)]);
            float4 xb = x4[lane + 32 * (u + 1)];
            a1 += wb.x * xb.x + wb.y * xb.y + wb.z * xb.z + wb.w * xb.w;
        }
        if (u + 2 < N4) {
            float4 wc = __ldcs(&w4[lane + 32 * (u + 2)]);
            float4 xc = x4[lane + 32 * (u + 2)];
            a2 += wc.x * xc.x + wc.y * xc.y + wc.z * xc.z + wc.w * xc.w;
        }
        if (u + 3 < N4) {
            float4 wd = __ldcs(&w4[lane + 32 * (u + 3)]);
            float4 xd = x4[lane + 32 * (u + 3)];
            a3 += wd.x * xd.x + wd.y * xd.y + wd.z * xd.z + wd.w * xd.w;
        }
    }
    float acc = (a0 + a1) + (a2 + a3);
    #pragma unroll
    for (int o = 16; o; o >>= 1) acc += __shfl_down_sync(0xFFFFFFFFu, acc, o);
    return acc;
}

// L2-prime one 4KB row: 4 LDG.32, one 32B sector per lane per instr.
// Default (.ca-class) policy so lines persist in L2 for the next stage.
__device__ __forceinline__ float prime_row(const float* __restrict__ row, int lane) {
    float acc = 0.f;
    #pragma unroll
    for (int i = 0; i < 4; i++)
        acc += __ldg(row + ((i * 32 + lane) << 3));   // stride 32B
    return acc;
}

__device__ __forceinline__ void cpa16(float* smem_dst, const float* g) {
    unsigned saddr = (unsigned)__cvta_generic_to_shared(smem_dst);
    asm volatile("cp.async.cg.shared.global [%0], [%1], 16;" :: "r"(saddr), "l"(g));
}

__device__ __forceinline__ const float* par_src(const P& p, int l, int a) {
    const float* st = p.state + (size_t)l * 5 * E;
    switch (a) {
        case 0:  return p.ln1w + l * E;
        case 1:  return p.ln1b + l * E;
        case 2:  return p.tmk + l * E;
        case 3:  return p.tmv + l * E;
        case 4:  return p.tmr + l * E;
        case 5:  return st + E;
        case 6:  return p.tf + l * E;
        case 7:  return p.td + l * E;
        case 8:  return st + 2 * E;
        case 9:  return st + 3 * E;
        case 10: return st + 4 * E;
        case 11: return p.ln2w + l * E;
        case 12: return p.ln2b + l * E;
        case 13: return p.ftmk + l * E;
        case 14: return p.ftmr + l * E;
        default: return st;
    }
}

__device__ __forceinline__ void prefetch_layer(const P& p, int l1, float* dst) {
    if (l1 < NL) {
        for (int t = threadIdx.x; t < NPAR * 256; t += T) {
            int a = t >> 8, i = (t & 255) << 2;
            cpa16(dst + a * E + i, par_src(p, l1, a) + i);
        }
    } else if (l1 == NL) {
        for (int t = threadIdx.x; t < 512; t += T) {
            int a = t >> 8, i = (t & 255) << 2;
            cpa16(dst + a * E + i, (a ? p.lnoutb : p.lnoutw) + i);
        }
    }
    asm volatile("cp.async.commit_group;" ::: "memory");
}

#define CP_WAIT() asm volatile("cp.async.wait_group 0;" ::: "memory")

#define SMEM_FLOATS (E + HH + 128 + 2 * NPAR * E)

__global__ void __launch_bounds__(T, 1) rwkv_kernel(P p) {
    extern __shared__ float smem[];
    float* sx   = smem;
    float* sop  = smem + E;
    float* sred = smem + E + HH;
    float* par0 = smem + E + HH + 128;

    const int tid = threadIdx.x, lane = tid & 31, warp = tid >> 5;
    const int gw = blockIdx.x * WPB + warp;
    const int NW = p.nb * WPB;
    const bool w0 = (p.ws && blockIdx.x == 0);
    float* outS = p.out + NV;
    int buf = 0;
    float pacc = 0.f;    // primer sink accumulator (never observably used)

    prefetch_layer(p, 0, par0);

    float s = 0.f, s2 = 0.f;
    for (int i = tid; i < E; i += T) { float v = p.ctx[i]; sop[i] = v; s += v; s2 += v * v; }
    block_reduce2(s, s2, sred);
    {
        float mu = s * (1.f / E);
        float rs = rsqrtf(s2 * (1.f / E) - mu * mu + 1e-5f);
        for (int i = tid; i < E; i += T)
            sx[i] = (sop[i] - mu) * rs * p.ln0w[i] + p.ln0b[i];
    }
    CP_WAIT();
    __syncthreads();

    for (int l = 0; l < NL; l++) {
        const float* pr = par0 + buf * NPAR * E;

        // ======== Stage A: combine prev FFN + LN1 + time-mix + k/v/r GEMV ========
        if (l > 0) {
            for (int i = tid; i < E; i += T) {
                float fr = 1.f / (1.f + __expf(-(g_frp[0][i] + g_frp[1][i])));
                sx[i] += fr * (g_fvp[0][i] + g_fvp[1][i] + g_fvp[2][i] + g_fvp[3][i]);
            }
        }
        s = 0.f; s2 = 0.f;
        for (int i = tid; i < E; i += T) { float v = sx[i]; s += v; s2 += v * v; }
        block_reduce2(s, s2, sred);
        {
            float mu = s * (1.f / E);
            float rs = rsqrtf(s2 * (1.f / E) - mu * mu + 1e-5f);
            for (int i = tid; i < E; i += T) {
                float xn = (sx[i] - mu) * rs * pr[0 * E + i] + pr[1 * E + i];
                float spv = pr[5 * E + i];
                float a = pr[2 * E + i], b = pr[3 * E + i], c = pr[4 * E + i];
                sop[i]         = xn * a + spv * (1.f - a);
                sop[E + i]     = xn * b + spv * (1.f - b);
                sop[2 * E + i] = xn * c + spv * (1.f - c);
                if (w0) outS[(size_t)(5 * l + 1) * E + i] = xn;
            }
        }
        __syncthreads();
        prefetch_layer(p, l + 1, par0 + (buf ^ 1) * NPAR * E);
        if (gw < 3072) {
            int m = gw >> 10, i = gw & 1023;
            const float* W = (m == 0 ? p.kw : (m == 1 ? p.vw : p.rw)) + (size_t)l * E * E;
            float acc = warp_dot<8>(W + (size_t)i * E, sop + (m << 10), lane);
            if (lane == 0) g_kvr[gw] = acc;
        } else {
            // A-idlers (1792 warps) prime stage B (ow: 1024 rows) + stage C
            // (fkw: 4096 rows, frw: 1024 rows) = 6144 rows
            const float* OW = p.ow + (size_t)l * E * E;
            const float* FK = p.fkw + (size_t)l * HH * E;
            const float* FR = p.frw + (size_t)l * E * E;
            for (int t = gw - 3072; t < 6144; t += 1792) {
                const float* rowp = (t < 1024) ? OW + (size_t)t * E
                                 : (t < 5120) ? FK + (size_t)(t - 1024) * E
                                              : FR + (size_t)(t - 5120) * E;
                pacc += prime_row(rowp, lane);
            }
        }
        grid_sync(p.nb);

        // ======== Stage B: WKV + ow GEMV (half rows) ========
        {
            for (int i = tid; i < E; i += T) {
                float k  = g_kvr[i];
                float v  = g_kvr[E + i];
                float rr = g_kvr[2 * E + i];
                float A = pr[8 * E + i], B = pr[9 * E + i], Pp = pr[10 * E + i];
                float ww = pr[6 * E + i] + k;
                float q = fmaxf(Pp, ww);
                float e1 = __expf(Pp - q), e2 = __expf(ww - q);
                float num = e1 * A + e2 * v, den = e1 * B + e2;
                float r = 1.f / (1.f + __expf(-rr));
                sop[i] = r * num / den;
                if (w0) {
                    float ww2 = Pp + pr[7 * E + i];
                    float p2 = fmaxf(ww2, k);
                    float e1b = __expf(ww2 - p2), e2b = __expf(k - p2);
                    outS[(size_t)(5 * l + 2) * E + i] = e1b * A + e2b * v;
                    outS[(size_t)(5 * l + 3) * E + i] = e1b * B + e2b;
                    outS[(size_t)(5 * l + 4) * E + i] = p2;
                }
            }
        }
        __syncthreads();
        if (gw < 2048) {
            int h = gw & 1, i = gw >> 1;
            const float* OW = p.ow + (size_t)l * E * E;
            float acc = warp_dot<4>(OW + (size_t)i * E + h * 512, sop + h * 512, lane);
            if (lane == 0) g_op[h][i] = acc;
        } else {
            // B-idlers (2816 warps) prime stage D (fvw: 1024 rows of 16KB = 4096
            // 4KB chunks)
            const float* FV = p.fvw + (size_t)l * E * HH;
            for (int t = gw - 2048; t < 4096; t += 2816)
                pacc += prime_row(FV + (size_t)t * E, lane);
        }
        grid_sync(p.nb);

        // ======== Stage C: x += ow; LN2 + chan-mix + fk (whole) / fr (half) ========
        for (int i = tid; i < E; i += T) sx[i] += g_op[0][i] + g_op[1][i];
        s = 0.f; s2 = 0.f;
        for (int i = tid; i < E; i += T) { float v = sx[i]; s += v; s2 += v * v; }
        block_reduce2(s, s2, sred);
        {
            float mu = s * (1.f / E);
            float rs = rsqrtf(s2 * (1.f / E) - mu * mu + 1e-5f);
            for (int i = tid; i < E; i += T) {
                float xn2 = (sx[i] - mu) * rs * pr[11 * E + i] + pr[12 * E + i];
                float sv = pr[15 * E + i];
                float a = pr[13 * E + i], b = pr[14 * E + i];
                sop[i]     = xn2 * a + sv * (1.f - a);
                sop[E + i] = xn2 * b + sv * (1.f - b);
                if (w0) outS[(size_t)(5 * l + 0) * E + i] = xn2;
            }
        }
        __syncthreads();
        {
            const float* FK = p.fkw + (size_t)l * HH * E;
            const float* FR = p.frw + (size_t)l * E * E;
            if (gw < 4096) {
                float acc = warp_dot<8>(FK + (size_t)gw * E, sop, lane);
                if (lane == 0) g_fk[gw] = acc;
            }
            int ft = (gw >= 4096) ? (gw - 4096) : (gw < 1280 ? 768 + gw : -1);
            if (ft >= 0 && ft < 2048) {
                int i = ft >> 1, h = ft & 1;
                float acc = warp_dot<4>(FR + (size_t)i * E + h * 512, sop + E + h * 512, lane);
                if (lane == 0) g_frp[h][i] = acc;
            }
        }
        grid_sync(p.nb);

        // ======== Stage D: kk = relu^2(fk); fv GEMV (quarter rows) ========
        for (int i = tid; i < HH; i += T) {
            float a = fmaxf(g_fk[i], 0.f);
            sop[i] = a * a;
        }
        __syncthreads();
        if (gw < 4096) {
            int c = gw & 3, i = gw >> 2;
            const float* FV = p.fvw + (size_t)l * E * HH;
            float acc = warp_dot<8>(FV + (size_t)i * HH + c * E, sop + c * E, lane);
            if (lane == 0) g_fvp[c][i] = acc;
        } else {
            // D-idlers (768 warps): prime next layer's kvr (3072 rows), or the
            // first head rows on the last layer
            if (l + 1 < NL) {
                const float* Wk = p.kw + (size_t)(l + 1) * E * E;
                const float* Wv = p.vw + (size_t)(l + 1) * E * E;
                const float* Wr = p.rw + (size_t)(l + 1) * E * E;
                for (int t = gw - 4096; t < 3072; t += 768) {
                    int m = t >> 10, i = t & 1023;
                    const float* W = (m == 0 ? Wk : (m == 1 ? Wv : Wr)) + (size_t)i * E;
                    pacc += prime_row(W, lane);
                }
            } else {
                for (int t = gw - 4096; t < 3072; t += 768)
                    pacc += prime_row(p.head + (size_t)t * E, lane);
            }
        }
        grid_sync(p.nb);

        CP_WAIT();
        buf ^= 1;
    }

    // primer sink: never true at runtime (finite weights), prevents DCE
    if (__isnanf(pacc)) g_sink = pacc;

    // ======== final: combine last FFN, LN_out, head GEMV ========
    const float* pr = par0 + buf * NPAR * E;
    for (int i = tid; i < E; i += T) {
        float fr = 1.f / (1.f + __expf(-(g_frp[0][i] + g_frp[1][i])));
        sx[i] += fr * (g_fvp[0][i] + g_fvp[1][i] + g_fvp[2][i] + g_fvp[3][i]);
    }
    s = 0.f; s2 = 0.f;
    for (int i = tid; i < E; i += T) { float v = sx[i]; s += v; s2 += v * v; }
    block_reduce2(s, s2, sred);
    {
        float mu = s * (1.f / E);
        float rs = rsqrtf(s2 * (1.f / E) - mu * mu + 1e-5f);
        for (int i = tid; i < E; i += T)
            sop[i] = (sx[i] - mu) * rs * pr[i] + pr[E + i];
    }
    __syncthreads();
    for (int t = gw; t < NV; t += NW) {
        float acc = warp_dot<8>(p.head + (size_t)t * E, sop, lane);
        if (lane == 0) p.out[t] = acc;
    }
}

extern "C" void kernel_launch(void* const* d_in, const int* in_sizes, int n_in,
                              void* d_out, int out_size) {
    (void)in_sizes; (void)n_in;
    P p;
    p.ctx    = (const float*)d_in[0];
    p.state  = (const float*)d_in[1];
    p.ln0w   = (const float*)d_in[2];
    p.ln0b   = (const float*)d_in[3];
    p.ln1w   = (const float*)d_in[4];
    p.ln1b   = (const float*)d_in[5];
    p.ln2w   = (const float*)d_in[6];
    p.ln2b   = (const float*)d_in[7];
    p.td     = (const float*)d_in[8];
    p.tf     = (const float*)d_in[9];
    p.tmk    = (const float*)d_in[10];
    p.tmv    = (const float*)d_in[11];
    p.tmr    = (const float*)d_in[12];
    p.kw     = (const float*)d_in[13];
    p.vw     = (const float*)d_in[14];
    p.rw     = (const float*)d_in[15];
    p.ow     = (const float*)d_in[16];
    p.ftmk   = (const float*)d_in[17];
    p.ftmr   = (const float*)d_in[18];
    p.fkw    = (const float*)d_in[19];
    p.frw    = (const float*)d_in[20];
    p.fvw    = (const float*)d_in[21];
    p.lnoutw = (const float*)d_in[22];
    p.lnoutb = (const float*)d_in[23];
    p.head   = (const float*)d_in[24];
    p.out    = (float*)d_out;

    int dev = 0;
    cudaGetDevice(&dev);
    int nsm = 0;
    cudaDeviceGetAttribute(&nsm, cudaDevAttrMultiProcessorCount, dev);
    if (nsm <= 0) nsm = 148;
    if (nsm > 256) nsm = 256;
    p.nb = nsm;
    p.ws = (out_size >= NV + 5 * NL * E) ? 1 : 0;

    cudaFuncSetAttribute(rwkv_kernel, cudaFuncAttributeMaxDynamicSharedMemorySize,
                         SMEM_FLOATS * sizeof(float));

    void* baddr = nullptr;
    cudaGetSymbolAddress(&baddr, g_bar);
    cudaMemsetAsync(baddr, 0, sizeof(unsigned int) * 2, 0);

    rwkv_kernel<<<nsm, T, SMEM_FLOATS * sizeof(float)>>>(p);
}

// round 15
// speedup vs baseline: 1.0505x; 1.0505x over previous
#include <cuda_runtime.h>
#include <cstdint>

// RWKV v4 single-token forward, persistent kernel, round 15.
// Model (validated over 14 rounds): LDG path is hard-capped at ~2.4TB/s by the
// per-SM LSU accept rate (1.82cyc/LDG, width-independent). R5 is at ~97% of
// that floor. This round adds bandwidth on the ONLY non-LSU path: one large
// cp.async.bulk (TMA) per block per layer carries the ENTIRE stage-D weight
// block (fvw rows are block-contiguous: ~108KB), issued at layer top (~13us
// ahead), consumed via LDS dots after a single fast-path mbarrier wait.
// LDG engine keeps 100% of stages A/B/C (never undersubscribed - the R12 bug).

#define E    1024
#define HH   4096
#define NL   24
#define NV   50277
#define T    1024
#define WPB  32
#define NPAR 16
#define FVCAP 28   // max TMA-staged 4KB vrows per block (nb>=147 -> <=28)

// ---- persistent device scratch ----
__device__ float g_kvr[3 * E];
__device__ float g_op[2][E];
__device__ float g_fk[HH];
__device__ float g_frp[2][E];
__device__ float g_fvp[4][E];
__device__ unsigned int g_bar[2];  // {count, generation}; memset per launch

struct P {
    const float *ctx, *state, *ln0w, *ln0b, *ln1w, *ln1b, *ln2w, *ln2b;
    const float *td, *tf, *tmk, *tmv, *tmr, *kw, *vw, *rw, *ow;
    const float *ftmk, *ftmr, *fkw, *frw, *fvw, *lnoutw, *lnoutb, *head;
    float* out;
    int nb;
    int ws;
};

__device__ __forceinline__ void grid_sync(int nb) {
    __syncthreads();
    if (threadIdx.x == 0) {
        unsigned int gen = ((volatile unsigned int*)g_bar)[1];
        __threadfence();
        if (atomicAdd(&g_bar[0], 1u) == (unsigned int)(nb - 1)) {
            atomicExch(&g_bar[0], 0u);
            __threadfence();
            atomicAdd(&g_bar[1], 1u);
        } else {
            while (((volatile unsigned int*)g_bar)[1] == gen) { __nanosleep(64); }
        }
        __threadfence();
    }
    __syncthreads();
}

__device__ __forceinline__ void block_reduce2(float& a, float& b, float* sr) {
    #pragma unroll
    for (int o = 16; o; o >>= 1) {
        a += __shfl_down_sync(0xFFFFFFFFu, a, o);
        b += __shfl_down_sync(0xFFFFFFFFu, b, o);
    }
    int w = threadIdx.x >> 5, l = threadIdx.x & 31;
    __syncthreads();
    if (l == 0) { sr[w] = a; sr[w + WPB] = b; }
    __syncthreads();
    if (threadIdx.x == 0) {
        float sa = 0.f, sb2 = 0.f;
        #pragma unroll
        for (int i = 0; i < WPB; i++) { sa += sr[i]; sb2 += sr[i + WPB]; }
        sr[2 * WPB] = sa; sr[2 * WPB + 1] = sb2;
    }
    __syncthreads();
    a = sr[2 * WPB];
    b = sr[2 * WPB + 1];
}

// global warp dot over 128*N4 floats (.cs read-once)
template <int N4>
__device__ __forceinline__ float warp_dot(const float* __restrict__ w,
                                          const float* x, int lane) {
    const float4* __restrict__ w4 = (const float4*)w;
    const float4* x4 = (const float4*)x;
    float a0 = 0.f, a1 = 0.f, a2 = 0.f, a3 = 0.f;
    #pragma unroll
    for (int u = 0; u < N4; u += 4) {
        float4 wa = __ldcs(&w4[lane + 32 * u]);
        float4 xa = x4[lane + 32 * u];
        a0 += wa.x * xa.x + wa.y * xa.y + wa.z * xa.z + wa.w * xa.w;
        if (u + 1 < N4) {
            float4 wb = __ldcs(&w4[lane + 32 * (u + 1)]);
            float4 xb = x4[lane + 32 * (u + 1)];
            a1 += wb.x * xb.x + wb.y * xb.y + wb.z * xb.z + wb.w * xb.w;
        }
        if (u + 2 < N4) {
            float4 wc = __ldcs(&w4[lane + 32 * (u + 2)]);
            float4 xc = x4[lane + 32 * (u + 2)];
            a2 += wc.x * xc.x + wc.y * xc.y + wc.z * xc.z + wc.w * xc.w;
        }
        if (u + 3 < N4) {
            float4 wd = __ldcs(&w4[lane + 32 * (u + 3)]);
            float4 xd = x4[lane + 32 * (u + 3)];
            a3 += wd.x * xd.x + wd.y * xd.y + wd.z * xd.z + wd.w * xd.w;
        }
    }
    float acc = (a0 + a1) + (a2 + a3);
    #pragma unroll
    for (int o = 16; o; o >>= 1) acc += __shfl_down_sync(0xFFFFFFFFu, acc, o);
    return acc;
}

// smem warp dot over 1024 floats
__device__ __forceinline__ float dot_s(const float* w, const float* x, int lane) {
    const float4* w4 = (const float4*)w;
    const float4* x4 = (const float4*)x;
    float a0 = 0.f, a1 = 0.f, a2 = 0.f, a3 = 0.f;
    #pragma unroll
    for (int u = 0; u < 8; u += 4) {
        float4 wa = w4[lane + 32 * u];       float4 xa = x4[lane + 32 * u];
        float4 wb = w4[lane + 32 * (u + 1)]; float4 xb = x4[lane + 32 * (u + 1)];
        float4 wc = w4[lane + 32 * (u + 2)]; float4 xc = x4[lane + 32 * (u + 2)];
        float4 wd = w4[lane + 32 * (u + 3)]; float4 xd = x4[lane + 32 * (u + 3)];
        a0 += wa.x * xa.x + wa.y * xa.y + wa.z * xa.z + wa.w * xa.w;
        a1 += wb.x * xb.x + wb.y * xb.y + wb.z * xb.z + wb.w * xb.w;
        a2 += wc.x * xc.x + wc.y * xc.y + wc.z * xc.z + wc.w * xc.w;
        a3 += wd.x * xd.x + wd.y * xd.y + wd.z * xd.z + wd.w * xd.w;
    }
    float acc = (a0 + a1) + (a2 + a3);
    #pragma unroll
    for (int o = 16; o; o >>= 1) acc += __shfl_down_sync(0xFFFFFFFFu, acc, o);
    return acc;
}

// ---- mbarrier / bulk-copy primitives ----
__device__ __forceinline__ void mb_init(uint32_t a, uint32_t cnt) {
    asm volatile("mbarrier.init.shared.b64 [%0], %1;" :: "r"(a), "r"(cnt) : "memory");
}
__device__ __forceinline__ void mb_expect(uint32_t a, uint32_t tx) {
    asm volatile("mbarrier.arrive.expect_tx.shared.b64 _, [%0], %1;" :: "r"(a), "r"(tx) : "memory");
}
__device__ __forceinline__ void mb_wait(uint32_t a, uint32_t parity) {
    uint32_t done;
    asm volatile(
        "{\n\t.reg .pred p;\n\t"
        "mbarrier.try_wait.parity.acquire.cta.shared::cta.b64 p, [%1], %2;\n\t"
        "selp.b32 %0, 1, 0, p;\n\t}"
        : "=r"(done) : "r"(a), "r"(parity) : "memory");
    if (!done) {
        asm volatile(
            "{\n\t.reg .pred P1;\n\t"
            "WAIT_LOOP_%=:\n\t"
            "mbarrier.try_wait.parity.acquire.cta.shared::cta.b64 P1, [%0], %1, 0x989680;\n\t"
            "@P1 bra.uni WAIT_DONE_%=;\n\t"
            "bra.uni WAIT_LOOP_%=;\n\t"
            "WAIT_DONE_%=:\n\t}"
            :: "r"(a), "r"(parity) : "memory");
    }
}
__device__ __forceinline__ void bulk_ld(uint32_t dst, const float* src, uint32_t bytes, uint32_t mbar) {
    asm volatile(
        "cp.async.bulk.shared::cluster.global.mbarrier::complete_tx::bytes [%0], [%1], %2, [%3];"
        :: "r"(dst), "l"(src), "r"(bytes), "r"(mbar) : "memory");
}

// ---- param staging (single buffer) ----
__device__ __forceinline__ void cpa16(float* smem_dst, const float* g) {
    unsigned saddr = (unsigned)__cvta_generic_to_shared(smem_dst);
    asm volatile("cp.async.cg.shared.global [%0], [%1], 16;" :: "r"(saddr), "l"(g));
}
__device__ __forceinline__ const float* par_src(const P& p, int l, int a) {
    const float* st = p.state + (size_t)l * 5 * E;
    switch (a) {
        case 0:  return p.ln1w + l * E;
        case 1:  return p.ln1b + l * E;
        case 2:  return p.tmk + l * E;
        case 3:  return p.tmv + l * E;
        case 4:  return p.tmr + l * E;
        case 5:  return st + E;
        case 6:  return p.tf + l * E;
        case 7:  return p.td + l * E;
        case 8:  return st + 2 * E;
        case 9:  return st + 3 * E;
        case 10: return st + 4 * E;
        case 11: return p.ln2w + l * E;
        case 12: return p.ln2b + l * E;
        case 13: return p.ftmk + l * E;
        case 14: return p.ftmr + l * E;
        default: return st;
    }
}
__device__ __forceinline__ void prefetch_layer(const P& p, int l1, float* dst) {
    if (l1 < NL) {
        for (int t = threadIdx.x; t < NPAR * 256; t += T) {
            int a = t >> 8, i = (t & 255) << 2;
            cpa16(dst + a * E + i, par_src(p, l1, a) + i);
        }
    } else if (l1 == NL) {
        for (int t = threadIdx.x; t < 512; t += T) {
            int a = t >> 8, i = (t & 255) << 2;
            cpa16(dst + a * E + i, (a ? p.lnoutb : p.lnoutw) + i);
        }
    }
    asm volatile("cp.async.commit_group;" ::: "memory");
}
#define CP_WAIT() asm volatile("cp.async.wait_group 0;" ::: "memory")

// smem: sx[E] + sop[HH] + sred[128] + par[NPAR*E] + fvbuf[FVCAP*E] + mbar pad
#define SMEM_FLOATS (E + HH + 128 + NPAR * E + FVCAP * E + 8)

__global__ void __launch_bounds__(T, 1) rwkv_kernel(P p) {
    extern __shared__ float smem[];
    float* sx    = smem;                                // [E]
    float* sop   = smem + E;                            // [HH]
    float* sred  = smem + E + HH;                       // [128]
    float* par   = smem + E + HH + 128;                 // [NPAR*E]
    float* fvbuf = smem + E + HH + 128 + NPAR * E;      // [FVCAP*E]
    float* mbsto = fvbuf + FVCAP * E;                   // mbarrier storage (8B)

    const int tid = threadIdx.x, lane = tid & 31, warp = tid >> 5;
    const int gw = blockIdx.x * WPB + warp;
    const int NW = p.nb * WPB;
    const bool w0 = (p.ws && blockIdx.x == 0);
    float* outS = p.out + NV;

    uint32_t mbar, fv_u32;
    asm("{ .reg .u64 t; cvta.to.shared.u64 t, %1; cvt.u32.u64 %0, t; }"
        : "=r"(mbar) : "l"((void*)mbsto));
    asm("{ .reg .u64 t; cvta.to.shared.u64 t, %1; cvt.u32.u64 %0, t; }"
        : "=r"(fv_u32) : "l"((void*)fvbuf));
    if (tid == 0) mb_init(mbar, 1);
    __syncthreads();
    int fvph = 0;

    // stage-D (fvw) block-contiguous vrow range [ds, de); TMA-staged part [ds, ds+dn)
    const int ds = (int)(((long long)(4 * E) * blockIdx.x) / p.nb);
    const int de = (int)(((long long)(4 * E) * (blockIdx.x + 1)) / p.nb);
    int dn = de - ds; if (dn > FVCAP) dn = FVCAP;

    prefetch_layer(p, 0, par);

    float s = 0.f, s2 = 0.f;
    for (int i = tid; i < E; i += T) { float v = p.ctx[i]; sop[i] = v; s += v; s2 += v * v; }
    block_reduce2(s, s2, sred);
    {
        float mu = s * (1.f / E);
        float rs = rsqrtf(s2 * (1.f / E) - mu * mu + 1e-5f);
        for (int i = tid; i < E; i += T)
            sx[i] = (sop[i] - mu) * rs * p.ln0w[i] + p.ln0b[i];
    }
    CP_WAIT();
    __syncthreads();

    for (int l = 0; l < NL; l++) {
        // ---- issue this layer's fvw block via ONE bulk TMA (window = A+B+C) ----
        if (tid == 0 && dn > 0) {
            mb_expect(mbar, (uint32_t)dn * 4096u);
            bulk_ld(fv_u32, p.fvw + (size_t)l * E * HH + (size_t)ds * E,
                    (uint32_t)dn * 4096u, mbar);
        }

        // ======== Stage A: combine prev FFN + LN1 + time-mix + k/v/r GEMV ========
        if (l > 0) {
            for (int i = tid; i < E; i += T) {
                float fr = 1.f / (1.f + __expf(-(g_frp[0][i] + g_frp[1][i])));
                sx[i] += fr * (g_fvp[0][i] + g_fvp[1][i] + g_fvp[2][i] + g_fvp[3][i]);
            }
        }
        s = 0.f; s2 = 0.f;
        for (int i = tid; i < E; i += T) { float v = sx[i]; s += v; s2 += v * v; }
        block_reduce2(s, s2, sred);
        {
            float mu = s * (1.f / E);
            float rs = rsqrtf(s2 * (1.f / E) - mu * mu + 1e-5f);
            for (int i = tid; i < E; i += T) {
                float xn = (sx[i] - mu) * rs * par[0 * E + i] + par[1 * E + i];
                float spv = par[5 * E + i];
                float a = par[2 * E + i], b = par[3 * E + i], c = par[4 * E + i];
                sop[i]         = xn * a + spv * (1.f - a);
                sop[E + i]     = xn * b + spv * (1.f - b);
                sop[2 * E + i] = xn * c + spv * (1.f - c);
                if (w0) outS[(size_t)(5 * l + 1) * E + i] = xn;
            }
        }
        __syncthreads();
        if (gw < 3072) {
            int m = gw >> 10, i = gw & 1023;
            const float* W = (m == 0 ? p.kw : (m == 1 ? p.vw : p.rw)) + (size_t)l * E * E;
            float acc = warp_dot<8>(W + (size_t)i * E, sop + (m << 10), lane);
            if (lane == 0) g_kvr[gw] = acc;
        }
        grid_sync(p.nb);

        // ======== Stage B: WKV + ow GEMV (half rows) ========
        {
            for (int i = tid; i < E; i += T) {
                float k  = g_kvr[i];
                float v  = g_kvr[E + i];
                float rr = g_kvr[2 * E + i];
                float A = par[8 * E + i], B = par[9 * E + i], Pp = par[10 * E + i];
                float ww = par[6 * E + i] + k;
                float q = fmaxf(Pp, ww);
                float e1 = __expf(Pp - q), e2 = __expf(ww - q);
                float num = e1 * A + e2 * v, den = e1 * B + e2;
                float r = 1.f / (1.f + __expf(-rr));
                sop[i] = r * num / den;
                if (w0) {
                    float ww2 = Pp + par[7 * E + i];
                    float p2 = fmaxf(ww2, k);
                    float e1b = __expf(ww2 - p2), e2b = __expf(k - p2);
                    outS[(size_t)(5 * l + 2) * E + i] = e1b * A + e2b * v;
                    outS[(size_t)(5 * l + 3) * E + i] = e1b * B + e2b;
                    outS[(size_t)(5 * l + 4) * E + i] = p2;
                }
            }
        }
        __syncthreads();
        if (gw < 2048) {
            int h = gw & 1, i = gw >> 1;
            const float* OW = p.ow + (size_t)l * E * E;
            float acc = warp_dot<4>(OW + (size_t)i * E + h * 512, sop + h * 512, lane);
            if (lane == 0) g_op[h][i] = acc;
        }
        grid_sync(p.nb);

        // ======== Stage C: x += ow; LN2 + chan-mix + fk (whole) / fr (half) ========
        for (int i = tid; i < E; i += T) sx[i] += g_op[0][i] + g_op[1][i];
        s = 0.f; s2 = 0.f;
        for (int i = tid; i < E; i += T) { float v = sx[i]; s += v; s2 += v * v; }
        block_reduce2(s, s2, sred);
        {
            float mu = s * (1.f / E);
            float rs = rsqrtf(s2 * (1.f / E) - mu * mu + 1e-5f);
            for (int i = tid; i < E; i += T) {
                float xn2 = (sx[i] - mu) * rs * par[11 * E + i] + par[12 * E + i];
                float sv = par[15 * E + i];
                float a = par[13 * E + i], b = par[14 * E + i];
                sop[i]     = xn2 * a + sv * (1.f - a);
                sop[E + i] = xn2 * b + sv * (1.f - b);
                if (w0) outS[(size_t)(5 * l + 0) * E + i] = xn2;
            }
        }
        __syncthreads();
        prefetch_layer(p, l + 1, par);   // params' last use was just above
        {
            const float* FK = p.fkw + (size_t)l * HH * E;
            const float* FR = p.frw + (size_t)l * E * E;
            if (gw < 4096) {
                float acc = warp_dot<8>(FK + (size_t)gw * E, sop, lane);
                if (lane == 0) g_fk[gw] = acc;
            }
            int ft = (gw >= 4096) ? (gw - 4096) : (gw < 1280 ? 768 + gw : -1);
            if (ft >= 0 && ft < 2048) {
                int i = ft >> 1, h = ft & 1;
                float acc = warp_dot<4>(FR + (size_t)i * E + h * 512, sop + E + h * 512, lane);
                if (lane == 0) g_frp[h][i] = acc;
            }
        }
        grid_sync(p.nb);

        // ======== Stage D: kk = relu^2(fk); fv dots from TMA-staged smem ========
        for (int i = tid; i < HH; i += T) {
            float a = fmaxf(g_fk[i], 0.f);
            sop[i] = a * a;
        }
        __syncthreads();
        if (dn > 0) { mb_wait(mbar, (uint32_t)fvph); fvph ^= 1; }
        // staged rows [ds, ds+dn): LDS dots (no LDG-floor cost)
        for (int t = ds + warp; t < ds + dn; t += WPB) {
            int c = t & 3, i = t >> 2;
            float acc = dot_s(fvbuf + (t - ds) * E, sop + c * E, lane);
            if (lane == 0) g_fvp[c][i] = acc;
        }
        // any overflow rows beyond FVCAP (only if nb < 147): LDG fallback
        for (int t = ds + dn + warp; t < de; t += WPB) {
            int c = t & 3, i = t >> 2;
            const float* FV = p.fvw + (size_t)l * E * HH;
            float acc = warp_dot<8>(FV + (size_t)t * E, sop + c * E, lane);
            if (lane == 0) g_fvp[c][i] = acc;
        }
        grid_sync(p.nb);

        CP_WAIT();   // next-layer params resident
    }

    // ======== final: combine last FFN, LN_out, head GEMV ========
    for (int i = tid; i < E; i += T) {
        float fr = 1.f / (1.f + __expf(-(g_frp[0][i] + g_frp[1][i])));
        sx[i] += fr * (g_fvp[0][i] + g_fvp[1][i] + g_fvp[2][i] + g_fvp[3][i]);
    }
    s = 0.f; s2 = 0.f;
    for (int i = tid; i < E; i += T) { float v = sx[i]; s += v; s2 += v * v; }
    block_reduce2(s, s2, sred);
    {
        float mu = s * (1.f / E);
        float rs = rsqrtf(s2 * (1.f / E) - mu * mu + 1e-5f);
        for (int i = tid; i < E; i += T)
            sop[i] = (sx[i] - mu) * rs * par[i] + par[E + i];
    }
    __syncthreads();
    for (int t = gw; t < NV; t += NW) {
        float acc = warp_dot<8>(p.head + (size_t)t * E, sop, lane);
        if (lane == 0) p.out[t] = acc;
    }
}

extern "C" void kernel_launch(void* const* d_in, const int* in_sizes, int n_in,
                              void* d_out, int out_size) {
    (void)in_sizes; (void)n_in;
    P p;
    p.ctx    = (const float*)d_in[0];
    p.state  = (const float*)d_in[1];
    p.ln0w   = (const float*)d_in[2];
    p.ln0b   = (const float*)d_in[3];
    p.ln1w   = (const float*)d_in[4];
    p.ln1b   = (const float*)d_in[5];
    p.ln2w   = (const float*)d_in[6];
    p.ln2b   = (const float*)d_in[7];
    p.td     = (const float*)d_in[8];
    p.tf     = (const float*)d_in[9];
    p.tmk    = (const float*)d_in[10];
    p.tmv    = (const float*)d_in[11];
    p.tmr    = (const float*)d_in[12];
    p.kw     = (const float*)d_in[13];
    p.vw     = (const float*)d_in[14];
    p.rw     = (const float*)d_in[15];
    p.ow     = (const float*)d_in[16];
    p.ftmk   = (const float*)d_in[17];
    p.ftmr   = (const float*)d_in[18];
    p.fkw    = (const float*)d_in[19];
    p.frw    = (const float*)d_in[20];
    p.fvw    = (const float*)d_in[21];
    p.lnoutw = (const float*)d_in[22];
    p.lnoutb = (const float*)d_in[23];
    p.head   = (const float*)d_in[24];
    p.out    = (float*)d_out;

    int dev = 0;
    cudaGetDevice(&dev);
    int nsm = 0;
    cudaDeviceGetAttribute(&nsm, cudaDevAttrMultiProcessorCount, dev);
    if (nsm <= 0) nsm = 148;
    if (nsm > 256) nsm = 256;
    p.nb = nsm;
    p.ws = (out_size >= NV + 5 * NL * E) ? 1 : 0;

    cudaFuncSetAttribute(rwkv_kernel, cudaFuncAttributeMaxDynamicSharedMemorySize,
                         SMEM_FLOATS * sizeof(float));

    void* baddr = nullptr;
    cudaGetSymbolAddress(&baddr, g_bar);
    cudaMemsetAsync(baddr, 0, sizeof(unsigned int) * 2, 0);

    rwkv_kernel<<<nsm, T, SMEM_FLOATS * sizeof(float)>>>(p);
}

// round 16
// speedup vs baseline: 1.2026x; 1.1448x over previous
#include <cuda_runtime.h>

// RWKV v4 single-token forward, persistent kernel, round 16.
// EXACT R5 (best, 620us) with ONE change: weight streams use __ldcv
// (ld.global.cv — no L2 allocation) instead of __ldcs. Rationale: the kernel
// sits at ~97% of the 2.42TB/s LDG plateau; every structural lever is
// exhausted (TMA: 6 failures, prefetch/prime/MLP/balance: neutral). B300's
// own max-throughput LTS measurement used LDG.cv. Our pattern loses zero
// reuse under .cv (each 128B line consumed entirely by one warp instruction),
// and .cv removes L2 allocation work for the 1.45GB one-shot stream, leaving
// L2 to the hot inter-stage vectors. Single-token change for clean attribution.

#define E    1024
#define HH   4096
#define NL   24
#define NV   50277
#define T    1024
#define WPB  32
#define NPAR 16

// ---- persistent device scratch ----
__device__ float g_kvr[3 * E];     // k, v, r (whole rows, no partials)
__device__ float g_op[2][E];       // ow half-row partials
__device__ float g_fk[HH];         // ffn_k pre-relu (whole rows)
__device__ float g_frp[2][E];      // ffn_r half-row partials
__device__ float g_fvp[4][E];      // ffn_v quarter-row partials
__device__ unsigned int g_bar[2];  // {count, generation}; memset per launch

struct P {
    const float *ctx, *state, *ln0w, *ln0b, *ln1w, *ln1b, *ln2w, *ln2b;
    const float *td, *tf, *tmk, *tmv, *tmr, *kw, *vw, *rw, *ow;
    const float *ftmk, *ftmr, *fkw, *frw, *fvw, *lnoutw, *lnoutb, *head;
    float* out;
    int nb;
    int ws;
};

__device__ __forceinline__ void grid_sync(int nb) {
    __syncthreads();
    if (threadIdx.x == 0) {
        unsigned int gen = ((volatile unsigned int*)g_bar)[1];
        __threadfence();
        if (atomicAdd(&g_bar[0], 1u) == (unsigned int)(nb - 1)) {
            atomicExch(&g_bar[0], 0u);
            __threadfence();
            atomicAdd(&g_bar[1], 1u);
        } else {
            while (((volatile unsigned int*)g_bar)[1] == gen) { __nanosleep(64); }
        }
        __threadfence();
    }
    __syncthreads();
}

__device__ __forceinline__ void block_reduce2(float& a, float& b, float* sr) {
    #pragma unroll
    for (int o = 16; o; o >>= 1) {
        a += __shfl_down_sync(0xFFFFFFFFu, a, o);
        b += __shfl_down_sync(0xFFFFFFFFu, b, o);
    }
    int w = threadIdx.x >> 5, l = threadIdx.x & 31;
    __syncthreads();
    if (l == 0) { sr[w] = a; sr[w + WPB] = b; }
    __syncthreads();
    if (threadIdx.x == 0) {
        float sa = 0.f, sb2 = 0.f;
        #pragma unroll
        for (int i = 0; i < WPB; i++) { sa += sr[i]; sb2 += sr[i + WPB]; }
        sr[2 * WPB] = sa; sr[2 * WPB + 1] = sb2;
    }
    __syncthreads();
    a = sr[2 * WPB];
    b = sr[2 * WPB + 1];
}

// warp dot over 128*N4 floats; weights streamed with .cv (no L2 allocation;
// read-once stream, each 128B line consumed entirely by one warp instruction)
template <int N4>
__device__ __forceinline__ float warp_dot(const float* __restrict__ w,
                                          const float* x, int lane) {
    const float4* __restrict__ w4 = (const float4*)w;
    const float4* x4 = (const float4*)x;
    float a0 = 0.f, a1 = 0.f, a2 = 0.f, a3 = 0.f;
    #pragma unroll
    for (int u = 0; u < N4; u += 4) {
        float4 wa = __ldcv(&w4[lane + 32 * u]);
        float4 xa = x4[lane + 32 * u];
        a0 += wa.x * xa.x + wa.y * xa.y + wa.z * xa.z + wa.w * xa.w;
        if (u + 1 < N4) {
            float4 wb = __ldcv(&w4[lane + 32 * (u + 1)]);
            float4 xb = x4[lane + 32 * (u + 1)];
            a1 += wb.x * xb.x + wb.y * xb.y + wb.z * xb.z + wb.w * xb.w;
        }
        if (u + 2 < N4) {
            float4 wc = __ldcv(&w4[lane + 32 * (u + 2)]);
            float4 xc = x4[lane + 32 * (u + 2)];
            a2 += wc.x * xc.x + wc.y * xc.y + wc.z * xc.z + wc.w * xc.w;
        }
        if (u + 3 < N4) {
            float4 wd = __ldcv(&w4[lane + 32 * (u + 3)]);
            float4 xd = x4[lane + 32 * (u + 3)];
            a3 += wd.x * xd.x + wd.y * xd.y + wd.z * xd.z + wd.w * xd.w;
        }
    }
    float acc = (a0 + a1) + (a2 + a3);
    #pragma unroll
    for (int o = 16; o; o >>= 1) acc += __shfl_down_sync(0xFFFFFFFFu, acc, o);
    return acc;
}

__device__ __forceinline__ void cpa16(float* smem_dst, const float* g) {
    unsigned saddr = (unsigned)__cvta_generic_to_shared(smem_dst);
    asm volatile("cp.async.cg.shared.global [%0], [%1], 16;" :: "r"(saddr), "l"(g));
}

__device__ __forceinline__ const float* par_src(const P& p, int l, int a) {
    const float* st = p.state + (size_t)l * 5 * E;
    switch (a) {
        case 0:  return p.ln1w + l * E;
        case 1:  return p.ln1b + l * E;
        case 2:  return p.tmk + l * E;
        case 3:  return p.tmv + l * E;
        case 4:  return p.tmr + l * E;
        case 5:  return st + E;
        case 6:  return p.tf + l * E;
        case 7:  return p.td + l * E;
        case 8:  return st + 2 * E;
        case 9:  return st + 3 * E;
        case 10: return st + 4 * E;
        case 11: return p.ln2w + l * E;
        case 12: return p.ln2b + l * E;
        case 13: return p.ftmk + l * E;
        case 14: return p.ftmr + l * E;
        default: return st;
    }
}

__device__ __forceinline__ void prefetch_layer(const P& p, int l1, float* dst) {
    if (l1 < NL) {
        for (int t = threadIdx.x; t < NPAR * 256; t += T) {
            int a = t >> 8, i = (t & 255) << 2;
            cpa16(dst + a * E + i, par_src(p, l1, a) + i);
        }
    } else if (l1 == NL) {
        for (int t = threadIdx.x; t < 512; t += T) {
            int a = t >> 8, i = (t & 255) << 2;
            cpa16(dst + a * E + i, (a ? p.lnoutb : p.lnoutw) + i);
        }
    }
    asm volatile("cp.async.commit_group;" ::: "memory");
}

#define CP_WAIT() asm volatile("cp.async.wait_group 0;" ::: "memory")

#define SMEM_FLOATS (E + HH + 128 + 2 * NPAR * E)

__global__ void __launch_bounds__(T, 1) rwkv_kernel(P p) {
    extern __shared__ float smem[];
    float* sx   = smem;
    float* sop  = smem + E;
    float* sred = smem + E + HH;
    float* par0 = smem + E + HH + 128;

    const int tid = threadIdx.x, lane = tid & 31, warp = tid >> 5;
    const int gw = blockIdx.x * WPB + warp;
    const int NW = p.nb * WPB;
    const bool w0 = (p.ws && blockIdx.x == 0);
    float* outS = p.out + NV;
    int buf = 0;

    prefetch_layer(p, 0, par0);

    float s = 0.f, s2 = 0.f;
    for (int i = tid; i < E; i += T) { float v = p.ctx[i]; sop[i] = v; s += v; s2 += v * v; }
    block_reduce2(s, s2, sred);
    {
        float mu = s * (1.f / E);
        float rs = rsqrtf(s2 * (1.f / E) - mu * mu + 1e-5f);
        for (int i = tid; i < E; i += T)
            sx[i] = (sop[i] - mu) * rs * p.ln0w[i] + p.ln0b[i];
    }
    CP_WAIT();
    __syncthreads();

    for (int l = 0; l < NL; l++) {
        const float* pr = par0 + buf * NPAR * E;

        // ======== Stage A: combine prev FFN + LN1 + time-mix + k/v/r GEMV ========
        if (l > 0) {
            for (int i = tid; i < E; i += T) {
                float fr = 1.f / (1.f + __expf(-(g_frp[0][i] + g_frp[1][i])));
                sx[i] += fr * (g_fvp[0][i] + g_fvp[1][i] + g_fvp[2][i] + g_fvp[3][i]);
            }
        }
        s = 0.f; s2 = 0.f;
        for (int i = tid; i < E; i += T) { float v = sx[i]; s += v; s2 += v * v; }
        block_reduce2(s, s2, sred);
        {
            float mu = s * (1.f / E);
            float rs = rsqrtf(s2 * (1.f / E) - mu * mu + 1e-5f);
            for (int i = tid; i < E; i += T) {
                float xn = (sx[i] - mu) * rs * pr[0 * E + i] + pr[1 * E + i];
                float spv = pr[5 * E + i];
                float a = pr[2 * E + i], b = pr[3 * E + i], c = pr[4 * E + i];
                sop[i]         = xn * a + spv * (1.f - a);
                sop[E + i]     = xn * b + spv * (1.f - b);
                sop[2 * E + i] = xn * c + spv * (1.f - c);
                if (w0) outS[(size_t)(5 * l + 1) * E + i] = xn;
            }
        }
        __syncthreads();
        prefetch_layer(p, l + 1, par0 + (buf ^ 1) * NPAR * E);
        if (gw < 3072) {
            int m = gw >> 10, i = gw & 1023;
            const float* W = (m == 0 ? p.kw : (m == 1 ? p.vw : p.rw)) + (size_t)l * E * E;
            float acc = warp_dot<8>(W + (size_t)i * E, sop + (m << 10), lane);
            if (lane == 0) g_kvr[gw] = acc;
        }
        grid_sync(p.nb);

        // ======== Stage B: WKV + ow GEMV (half rows) ========
        {
            for (int i = tid; i < E; i += T) {
                float k  = g_kvr[i];
                float v  = g_kvr[E + i];
                float rr = g_kvr[2 * E + i];
                float A = pr[8 * E + i], B = pr[9 * E + i], Pp = pr[10 * E + i];
                float ww = pr[6 * E + i] + k;
                float q = fmaxf(Pp, ww);
                float e1 = __expf(Pp - q), e2 = __expf(ww - q);
                float num = e1 * A + e2 * v, den = e1 * B + e2;
                float r = 1.f / (1.f + __expf(-rr));
                sop[i] = r * num / den;
                if (w0) {
                    float ww2 = Pp + pr[7 * E + i];
                    float p2 = fmaxf(ww2, k);
                    float e1b = __expf(ww2 - p2), e2b = __expf(k - p2);
                    outS[(size_t)(5 * l + 2) * E + i] = e1b * A + e2b * v;
                    outS[(size_t)(5 * l + 3) * E + i] = e1b * B + e2b;
                    outS[(size_t)(5 * l + 4) * E + i] = p2;
                }
            }
        }
        __syncthreads();
        if (gw < 2048) {
            int h = gw & 1, i = gw >> 1;
            const float* OW = p.ow + (size_t)l * E * E;
            float acc = warp_dot<4>(OW + (size_t)i * E + h * 512, sop + h * 512, lane);
            if (lane == 0) g_op[h][i] = acc;
        }
        grid_sync(p.nb);

        // ======== Stage C: x += ow; LN2 + chan-mix + fk (whole) / fr (half) ========
        for (int i = tid; i < E; i += T) sx[i] += g_op[0][i] + g_op[1][i];
        s = 0.f; s2 = 0.f;
        for (int i = tid; i < E; i += T) { float v = sx[i]; s += v; s2 += v * v; }
        block_reduce2(s, s2, sred);
        {
            float mu = s * (1.f / E);
            float rs = rsqrtf(s2 * (1.f / E) - mu * mu + 1e-5f);
            for (int i = tid; i < E; i += T) {
                float xn2 = (sx[i] - mu) * rs * pr[11 * E + i] + pr[12 * E + i];
                float sv = pr[15 * E + i];
                float a = pr[13 * E + i], b = pr[14 * E + i];
                sop[i]     = xn2 * a + sv * (1.f - a);
                sop[E + i] = xn2 * b + sv * (1.f - b);
                if (w0) outS[(size_t)(5 * l + 0) * E + i] = xn2;
            }
        }
        __syncthreads();
        {
            const float* FK = p.fkw + (size_t)l * HH * E;
            const float* FR = p.frw + (size_t)l * E * E;
            if (gw < 4096) {
                float acc = warp_dot<8>(FK + (size_t)gw * E, sop, lane);
                if (lane == 0) g_fk[gw] = acc;
            }
            // fr halves: 2048 tasks on warps [4096,4864) and [0,1280)
            int ft = (gw >= 4096) ? (gw - 4096) : (gw < 1280 ? 768 + gw : -1);
            if (ft >= 0 && ft < 2048) {
                int i = ft >> 1, h = ft & 1;
                float acc = warp_dot<4>(FR + (size_t)i * E + h * 512, sop + E + h * 512, lane);
                if (lane == 0) g_frp[h][i] = acc;
            }
        }
        grid_sync(p.nb);

        // ======== Stage D: kk = relu^2(fk); fv GEMV (quarter rows) ========
        for (int i = tid; i < HH; i += T) {
            float a = fmaxf(g_fk[i], 0.f);
            sop[i] = a * a;
        }
        __syncthreads();
        if (gw < 4096) {
            int c = gw & 3, i = gw >> 2;
            const float* FV = p.fvw + (size_t)l * E * HH;
            float acc = warp_dot<8>(FV + (size_t)i * HH + c * E, sop + c * E, lane);
            if (lane == 0) g_fvp[c][i] = acc;
        }
        grid_sync(p.nb);

        CP_WAIT();
        buf ^= 1;
    }

    // ======== final: combine last FFN, LN_out, head GEMV ========
    const float* pr = par0 + buf * NPAR * E;
    for (int i = tid; i < E; i += T) {
        float fr = 1.f / (1.f + __expf(-(g_frp[0][i] + g_frp[1][i])));
        sx[i] += fr * (g_fvp[0][i] + g_fvp[1][i] + g_fvp[2][i] + g_fvp[3][i]);
    }
    s = 0.f; s2 = 0.f;
    for (int i = tid; i < E; i += T) { float v = sx[i]; s += v; s2 += v * v; }
    block_reduce2(s, s2, sred);
    {
        float mu = s * (1.f / E);
        float rs = rsqrtf(s2 * (1.f / E) - mu * mu + 1e-5f);
        for (int i = tid; i < E; i += T)
            sop[i] = (sx[i] - mu) * rs * pr[i] + pr[E + i];
    }
    __syncthreads();
    for (int t = gw; t < NV; t += NW) {
        float acc = warp_dot<8>(p.head + (size_t)t * E, sop, lane);
        if (lane == 0) p.out[t] = acc;
    }
}

extern "C" void kernel_launch(void* const* d_in, const int* in_sizes, int n_in,
                              void* d_out, int out_size) {
    (void)in_sizes; (void)n_in;
    P p;
    p.ctx    = (const float*)d_in[0];
    p.state  = (const float*)d_in[1];
    p.ln0w   = (const float*)d_in[2];
    p.ln0b   = (const float*)d_in[3];
    p.ln1w   = (const float*)d_in[4];
    p.ln1b   = (const float*)d_in[5];
    p.ln2w   = (const float*)d_in[6];
    p.ln2b   = (const float*)d_in[7];
    p.td     = (const float*)d_in[8];
    p.tf     = (const float*)d_in[9];
    p.tmk    = (const float*)d_in[10];
    p.tmv    = (const float*)d_in[11];
    p.tmr    = (const float*)d_in[12];
    p.kw     = (const float*)d_in[13];
    p.vw     = (const float*)d_in[14];
    p.rw     = (const float*)d_in[15];
    p.ow     = (const float*)d_in[16];
    p.ftmk   = (const float*)d_in[17];
    p.ftmr   = (const float*)d_in[18];
    p.fkw    = (const float*)d_in[19];
    p.frw    = (const float*)d_in[20];
    p.fvw    = (const float*)d_in[21];
    p.lnoutw = (const float*)d_in[22];
    p.lnoutb = (const float*)d_in[23];
    p.head   = (const float*)d_in[24];
    p.out    = (float*)d_out;

    int dev = 0;
    cudaGetDevice(&dev);
    int nsm = 0;
    cudaDeviceGetAttribute(&nsm, cudaDevAttrMultiProcessorCount, dev);
    if (nsm <= 0) nsm = 148;
    if (nsm > 256) nsm = 256;
    p.nb = nsm;
    p.ws = (out_size >= NV + 5 * NL * E) ? 1 : 0;

    cudaFuncSetAttribute(rwkv_kernel, cudaFuncAttributeMaxDynamicSharedMemorySize,
                         SMEM_FLOATS * sizeof(float));

    void* baddr = nullptr;
    cudaGetSymbolAddress(&baddr, g_bar);
    cudaMemsetAsync(baddr, 0, sizeof(unsigned int) * 2, 0);

    rwkv_kernel<<<nsm, T, SMEM_FLOATS * sizeof(float)>>>(p);
}